// round 16
// baseline (speedup 1.0000x reference)
#include <cuda_runtime.h>
#include <cuda_bf16.h>
#include <cuda_fp16.h>
#include <math.h>
#include <cstdint>

// Problem dims
#define BV 32000
#define EMB 256
#define DU 512
#define BB 32
#define TIN 64
#define TOUT 64
#define BT (BB*TOUT)          // 2048
#define KIN (DU+EMB)          // 768

#define N_LOGITS  (BT*BV)
#define N_H       (BB*DU)

// ------------------------- scratch (static device globals) -------------------
__device__ float g_x[BT*EMB];
__device__ float g_q[BT*DU];
__device__ float g_att[BT*DU];
__device__ float g_zin[BT*4*DU];
__device__ float g_hs[TOUT*BB*DU];      // NEW layout: [t][d][b]
__device__ float g_WhP[128*512*16];
__device__ unsigned g_bar;

// bf16 split operands for Zin GEMM
__device__ __align__(16) __nv_bfloat16 g_lin_h[BT*KIN],  g_lin_l[BT*KIN];
__device__ __align__(16) __nv_bfloat16 g_Wx_h[KIN*4*DU], g_Wx_l[KIN*4*DU];

// fp16 operands for logits GEMM (A = fp16(hs) [b*TOUT+t][d], B = fp16(Wfc))
__device__ __align__(16) __half g_hs16[BT*DU];
__device__ __align__(16) __half g_Wfc16[(size_t)DU*BV];

// ------------------------- tiny kernels --------------------------------------
__global__ void zero_bar_kernel() { g_bar = 0u; }

__global__ void gather_x_kernel(const int* __restrict__ inp,
                                const float* __restrict__ emb) {
    int i = blockIdx.x * blockDim.x + threadIdx.x;
    if (i >= BT*EMB) return;
    int bt = i >> 8, e = i & 255;
    g_x[i] = emb[(size_t)inp[bt] * EMB + e];
}

__device__ __forceinline__ void split_store(float v, __nv_bfloat16* hi,
                                            __nv_bfloat16* lo, size_t i) {
    __nv_bfloat16 h = __float2bfloat16(v);
    hi[i] = h;
    lo[i] = __float2bfloat16(v - __bfloat162float(h));
}

__global__ void split_kernel(const float* __restrict__ in,
                             __nv_bfloat16* __restrict__ hi,
                             __nv_bfloat16* __restrict__ lo, int n) {
    int i = blockIdx.x * blockDim.x + threadIdx.x;
    if (i >= n) return;
    split_store(in[i], hi, lo, i);
}

__global__ void build_lstmin_split_kernel() {
    int i = blockIdx.x * blockDim.x + threadIdx.x;
    if (i >= BT*KIN) return;
    int bt = i / KIN, j = i % KIN;
    float v = (j < DU) ? g_att[bt*DU + j] : g_x[bt*EMB + (j-DU)];
    split_store(v, g_lin_h, g_lin_l, i);
}

__global__ void pack_wh_kernel(const float* __restrict__ Wh) {
    int i = blockIdx.x * blockDim.x + threadIdx.x;
    if (i >= 128*512*16) return;
    int blk = i >> 13;
    int rem = i & 8191;
    int k = rem >> 4, t = rem & 15;
    int q = t >> 2, j = t & 3;
    g_WhP[i] = Wh[(size_t)k*2048 + q*512 + blk*4 + j];
}

// Wfc [512, 32000] fp32 -> fp16 (same layout)
__global__ void wfc_f16_kernel(const float* __restrict__ Wfc) {
    size_t i = (size_t)blockIdx.x * blockDim.x + threadIdx.x;
    if (i >= (size_t)DU*BV) return;
    g_Wfc16[i] = __float2half_rn(Wfc[i]);
}

// ------------------------- scalar fp32 SGEMM (small q GEMM only) -------------
__global__ __launch_bounds__(256)
void sgemm_kernel(const float* __restrict__ A, const float* __restrict__ B,
                  const float* __restrict__ bias, float* __restrict__ C,
                  int M, int N, int K) {
    __shared__ float As[8][128];
    __shared__ float Bs[8][128];
    const int tid = threadIdx.x;
    const int tx = tid & 15, ty = tid >> 4;
    const int row0 = blockIdx.y * 128, col0 = blockIdx.x * 128;

    float acc[8][8];
#pragma unroll
    for (int i = 0; i < 8; i++)
#pragma unroll
        for (int j = 0; j < 8; j++) acc[i][j] = 0.f;

    for (int k0 = 0; k0 < K; k0 += 8) {
#pragma unroll
        for (int l = 0; l < 4; l++) {
            int idx = tid + l*256;
            int r = idx >> 3, kk = idx & 7;
            As[kk][r] = A[(size_t)(row0 + r) * K + k0 + kk];
        }
#pragma unroll
        for (int l = 0; l < 4; l++) {
            int idx = tid + l*256;
            int kk = idx >> 7, c = idx & 127;
            Bs[kk][c] = B[(size_t)(k0 + kk) * N + col0 + c];
        }
        __syncthreads();
#pragma unroll
        for (int kk = 0; kk < 8; kk++) {
            float a[8], b[8];
#pragma unroll
            for (int i = 0; i < 8; i++) a[i] = As[kk][ty*8 + i];
#pragma unroll
            for (int j = 0; j < 8; j++) b[j] = Bs[kk][tx*8 + j];
#pragma unroll
            for (int i = 0; i < 8; i++)
#pragma unroll
                for (int j = 0; j < 8; j++) acc[i][j] += a[i] * b[j];
        }
        __syncthreads();
    }
#pragma unroll
    for (int i = 0; i < 8; i++) {
        size_t r = row0 + ty*8 + i;
#pragma unroll
        for (int j = 0; j < 8; j++) {
            int cc = col0 + tx*8 + j;
            C[r * N + cc] = acc[i][j] + bias[cc];
        }
    }
}

// ------------------------- common PTX helpers --------------------------------
__device__ __forceinline__ uint32_t smem_u32(const void* p) {
    return (uint32_t)__cvta_generic_to_shared(p);
}
__device__ __forceinline__ void cp16(void* dst, const void* src) {
    uint32_t d = smem_u32(dst);
    asm volatile("cp.async.cg.shared.global [%0], [%1], 16;"
                 :: "r"(d), "l"(src) : "memory");
}
__device__ __forceinline__ void cp_commit() {
    asm volatile("cp.async.commit_group;" ::: "memory");
}
__device__ __forceinline__ void cp_wait1() {
    asm volatile("cp.async.wait_group 1;" ::: "memory");
}
__device__ __forceinline__ void ldsm_x4(unsigned* r, uint32_t addr) {
    asm volatile("ldmatrix.sync.aligned.m8n8.x4.shared.b16 {%0,%1,%2,%3}, [%4];"
                 : "=r"(r[0]), "=r"(r[1]), "=r"(r[2]), "=r"(r[3]) : "r"(addr));
}
__device__ __forceinline__ void ldsm_x4_t(unsigned* r, uint32_t addr) {
    asm volatile("ldmatrix.sync.aligned.m8n8.x4.trans.shared.b16 {%0,%1,%2,%3}, [%4];"
                 : "=r"(r[0]), "=r"(r[1]), "=r"(r[2]), "=r"(r[3]) : "r"(addr));
}
__device__ __forceinline__ void mma16816(float* c, const unsigned* a,
                                         unsigned b0, unsigned b1) {
    asm volatile(
        "mma.sync.aligned.m16n8k16.row.col.f32.bf16.bf16.f32 "
        "{%0,%1,%2,%3}, {%4,%5,%6,%7}, {%8,%9}, {%0,%1,%2,%3};"
        : "+f"(c[0]), "+f"(c[1]), "+f"(c[2]), "+f"(c[3])
        : "r"(a[0]), "r"(a[1]), "r"(a[2]), "r"(a[3]), "r"(b0), "r"(b1));
}
__device__ __forceinline__ void mma16816h(float* c, const unsigned* a,
                                          unsigned b0, unsigned b1) {
    asm volatile(
        "mma.sync.aligned.m16n8k16.row.col.f32.f16.f16.f32 "
        "{%0,%1,%2,%3}, {%4,%5,%6,%7}, {%8,%9}, {%0,%1,%2,%3};"
        : "+f"(c[0]), "+f"(c[1]), "+f"(c[2]), "+f"(c[3])
        : "r"(a[0]), "r"(a[1]), "r"(a[2]), "r"(a[3]), "r"(b0), "r"(b1));
}

// ------------------------- bf16x3 mma GEMM (Zin only) ------------------------
#define BKC 32
#define OFF_AL_B 10240
#define OFF_BH_B 20480
#define OFF_BL_B 29184
#define STAGE_B  37888
#define GEMM_SMEM (2*STAGE_B)

__device__ __forceinline__ void gemm_issue(
        const __nv_bfloat16* Ah, const __nv_bfloat16* Al,
        const __nv_bfloat16* Bh, const __nv_bfloat16* Bl,
        char* smc, int ch, int tid, int row0, int col0, int K, int N) {
    char* sb = smc + (ch & 1) * STAGE_B;
    const int k0 = ch * BKC;
#pragma unroll
    for (int l = 0; l < 2; l++) {
        int c = tid*2 + l;
        int r = c >> 2, q = c & 3;
        size_t g = (size_t)(row0 + r) * K + k0 + q*8;
        cp16(sb + r*80 + q*16, Ah + g);
        cp16(sb + OFF_AL_B + r*80 + q*16, Al + g);
    }
#pragma unroll
    for (int l = 0; l < 2; l++) {
        int c = tid*2 + l;
        int r = c >> 4, q = c & 15;
        size_t g = (size_t)(k0 + r) * N + col0 + q*8;
        cp16(sb + OFF_BH_B + r*272 + q*16, Bh + g);
        cp16(sb + OFF_BL_B + r*272 + q*16, Bl + g);
    }
    cp_commit();
}

__global__ __launch_bounds__(256, 2)
void gemm_mma3_kernel(const __nv_bfloat16* __restrict__ Ah,
                      const __nv_bfloat16* __restrict__ Al,
                      const __nv_bfloat16* __restrict__ Bh,
                      const __nv_bfloat16* __restrict__ Bl,
                      const float* __restrict__ bias,
                      float* __restrict__ C,
                      int M, int N, int K) {
    extern __shared__ char smc[];
    const uint32_t sbase = smem_u32(smc);
    const int tid  = threadIdx.x;
    const int lane = tid & 31;
    const int warp = tid >> 5;
    const int wm = warp & 1;
    const int wn = warp >> 1;
    const int row0 = blockIdx.x * 128;
    const int col0 = blockIdx.y * 128;

    float acc[4][4][4];
#pragma unroll
    for (int i = 0; i < 4; i++)
#pragma unroll
        for (int j = 0; j < 4; j++)
#pragma unroll
            for (int r = 0; r < 4; r++) acc[i][j][r] = 0.f;

    const int grp = lane >> 3;
    const unsigned a_row  = (lane & 15);
    const unsigned a_koff = (lane >> 4) << 3;
    const unsigned b_row  = ((grp & 1) << 3) + (lane & 7);
    const unsigned b_coff = wn*32 + ((grp >> 1) << 3);

    const int nch = K / BKC;
    gemm_issue(Ah, Al, Bh, Bl, smc, 0, tid, row0, col0, K, N);
    if (nch > 1) gemm_issue(Ah, Al, Bh, Bl, smc, 1, tid, row0, col0, K, N);
    else cp_commit();

    for (int ch = 0; ch < nch; ch++) {
        cp_wait1();
        __syncthreads();

        const uint32_t st = sbase + (ch & 1) * STAGE_B;
        const uint32_t aH = st, aL = st + OFF_AL_B;
        const uint32_t bH = st + OFF_BH_B, bL = st + OFF_BL_B;
#pragma unroll
        for (int kk = 0; kk < BKC; kk += 16) {
            unsigned b_h[2][4], b_l[2][4];
#pragma unroll
            for (int p = 0; p < 2; p++) {
                uint32_t off = ((kk + b_row) * 136 + b_coff + p*16) * 2;
                ldsm_x4_t(b_h[p], bH + off);
                ldsm_x4_t(b_l[p], bL + off);
            }
#pragma unroll
            for (int mt = 0; mt < 4; mt++) {
                unsigned a_h[4], a_l[4];
                uint32_t off = ((wm*64 + mt*16 + a_row) * 40 + kk + a_koff) * 2;
                ldsm_x4(a_h, aH + off);
                ldsm_x4(a_l, aL + off);
#pragma unroll
                for (int p = 0; p < 2; p++)
#pragma unroll
                    for (int hf = 0; hf < 2; hf++) {
                        int nt = p*2 + hf;
                        unsigned bh0 = b_h[p][hf*2], bh1 = b_h[p][hf*2+1];
                        unsigned bl0 = b_l[p][hf*2], bl1 = b_l[p][hf*2+1];
                        mma16816(acc[mt][nt], a_h, bh0, bh1);
                        mma16816(acc[mt][nt], a_h, bl0, bl1);
                        mma16816(acc[mt][nt], a_l, bh0, bh1);
                    }
            }
        }
        __syncthreads();
        if (ch + 2 < nch)
            gemm_issue(Ah, Al, Bh, Bl, smc, ch + 2, tid, row0, col0, K, N);
        else
            cp_commit();
    }

#pragma unroll
    for (int mt = 0; mt < 4; mt++) {
        int r_up = row0 + wm*64 + mt*16 + (lane >> 2);
        int r_dn = r_up + 8;
#pragma unroll
        for (int nt = 0; nt < 4; nt++) {
            int cc = col0 + wn*32 + nt*8 + (lane & 3)*2;
            float b0 = bias[cc], b1 = bias[cc+1];
            *(float2*)&C[(size_t)r_up * N + cc] =
                make_float2(acc[mt][nt][0] + b0, acc[mt][nt][1] + b1);
            *(float2*)&C[(size_t)r_dn * N + cc] =
                make_float2(acc[mt][nt][2] + b0, acc[mt][nt][3] + b1);
        }
    }
}

// ------------------------- fp16 single-pass mma GEMM (logits, R14 config) ----
#define F16_B   10240
#define F16_STG 18944
#define GEMM16_SMEM (3*F16_STG)

__device__ __forceinline__ void f16_issue(
        const __half* A, const __half* B,
        char* smc, int ch, int tid, int row0, int col0, int K, int N) {
    char* sb = smc + (ch % 3) * F16_STG;
    const int k0 = ch * BKC;
#pragma unroll
    for (int l = 0; l < 2; l++) {
        int c = tid*2 + l;                 // 0..511
        int r = c >> 2, q = c & 3;         // A: 128 rows x 4 x 16B
        size_t g = (size_t)(row0 + r) * K + k0 + q*8;
        cp16(sb + r*80 + q*16, A + g);
    }
#pragma unroll
    for (int l = 0; l < 2; l++) {
        int c = tid*2 + l;
        int r = c >> 4, q = c & 15;        // B: 32 rows x 16 x 16B
        size_t g = (size_t)(k0 + r) * N + col0 + q*8;
        cp16(sb + F16_B + r*272 + q*16, B + g);
    }
    cp_commit();
}

__global__ __launch_bounds__(256, 2)
void gemm_f16_kernel(const __half* __restrict__ A,
                     const __half* __restrict__ B,
                     const float* __restrict__ bias,
                     float* __restrict__ C,
                     int M, int N, int K) {
    extern __shared__ char smc[];
    const uint32_t sbase = smem_u32(smc);
    const int tid  = threadIdx.x;
    const int lane = tid & 31;
    const int warp = tid >> 5;
    const int wm = warp & 1;
    const int wn = warp >> 1;
    const int row0 = blockIdx.y * 128;
    const int col0 = blockIdx.x * 128;

    float acc[4][4][4];
#pragma unroll
    for (int i = 0; i < 4; i++)
#pragma unroll
        for (int j = 0; j < 4; j++)
#pragma unroll
            for (int r = 0; r < 4; r++) acc[i][j][r] = 0.f;

    const int grp = lane >> 3;
    const unsigned a_row  = (lane & 15);
    const unsigned a_koff = (lane >> 4) << 3;
    const unsigned b_row  = ((grp & 1) << 3) + (lane & 7);
    const unsigned b_coff = wn*32 + ((grp >> 1) << 3);

    const int nch = K / BKC;               // 16 for K=512
    f16_issue(A, B, smc, 0, tid, row0, col0, K, N);
    if (nch > 1) f16_issue(A, B, smc, 1, tid, row0, col0, K, N);
    else cp_commit();

    for (int ch = 0; ch < nch; ch++) {
        cp_wait1();
        __syncthreads();
        if (ch + 2 < nch)
            f16_issue(A, B, smc, ch + 2, tid, row0, col0, K, N);
        else
            cp_commit();

        const uint32_t st = sbase + (ch % 3) * F16_STG;
        const uint32_t aP = st;
        const uint32_t bP = st + F16_B;
#pragma unroll
        for (int kk = 0; kk < BKC; kk += 16) {
            unsigned b_f[2][4];
#pragma unroll
            for (int p = 0; p < 2; p++) {
                uint32_t off = ((kk + b_row) * 136 + b_coff + p*16) * 2;
                ldsm_x4_t(b_f[p], bP + off);
            }
#pragma unroll
            for (int mt = 0; mt < 4; mt++) {
                unsigned a_f[4];
                uint32_t off = ((wm*64 + mt*16 + a_row) * 40 + kk + a_koff) * 2;
                ldsm_x4(a_f, aP + off);
#pragma unroll
                for (int p = 0; p < 2; p++)
#pragma unroll
                    for (int hf = 0; hf < 2; hf++) {
                        int nt = p*2 + hf;
                        mma16816h(acc[mt][nt], a_f, b_f[p][hf*2], b_f[p][hf*2+1]);
                    }
            }
        }
        __syncthreads();
    }

#pragma unroll
    for (int mt = 0; mt < 4; mt++) {
        int r_up = row0 + wm*64 + mt*16 + (lane >> 2);
        int r_dn = r_up + 8;
#pragma unroll
        for (int nt = 0; nt < 4; nt++) {
            int cc = col0 + wn*32 + nt*8 + (lane & 3)*2;
            float b0 = bias[cc], b1 = bias[cc+1];
            *(float2*)&C[(size_t)r_up * N + cc] =
                make_float2(acc[mt][nt][0] + b0, acc[mt][nt][1] + b1);
            *(float2*)&C[(size_t)r_dn * N + cc] =
                make_float2(acc[mt][nt][2] + b0, acc[mt][nt][3] + b1);
        }
    }
}

// ------------------------- attention (one block per (b,t)) -------------------
__global__ __launch_bounds__(256)
void attn_kernel(const float* __restrict__ enc, float* __restrict__ attn_out) {
    int bt = blockIdx.x;
    int b = bt >> 6;
    __shared__ float sq[DU];
    __shared__ float sc[TIN];
    __shared__ float red[2];
    int tid = threadIdx.x;
    int w = tid >> 5, lane = tid & 31;

    for (int i = tid; i < DU; i += 256) sq[i] = g_q[(size_t)bt*DU + i];
    __syncthreads();

    const float* encb = enc + (size_t)b * TIN * DU;
    for (int s = w; s < TIN; s += 8) {
        const float* e = encb + (size_t)s * DU;
        float sum = 0.f;
        for (int d = lane; d < DU; d += 32) sum += sq[d] * e[d];
#pragma unroll
        for (int o = 16; o > 0; o >>= 1) sum += __shfl_xor_sync(0xffffffffu, sum, o);
        if (lane == 0) sc[s] = sum;
    }
    __syncthreads();

    if (w == 0) {
        float v = fmaxf(sc[lane], sc[lane + 32]);
#pragma unroll
        for (int o = 16; o > 0; o >>= 1) v = fmaxf(v, __shfl_xor_sync(0xffffffffu, v, o));
        if (lane == 0) red[0] = v;
    }
    __syncthreads();
    float m = red[0];
    if (tid < TIN) sc[tid] = expf(sc[tid] - m);
    __syncthreads();
    if (w == 0) {
        float v = sc[lane] + sc[lane + 32];
#pragma unroll
        for (int o = 16; o > 0; o >>= 1) v += __shfl_xor_sync(0xffffffffu, v, o);
        if (lane == 0) red[1] = v;
    }
    __syncthreads();
    float inv = 1.f / red[1];
    if (tid < TIN) {
        float wv = sc[tid] * inv;
        sc[tid] = wv;
        attn_out[(size_t)bt * TIN + tid] = wv;
    }
    __syncthreads();

    for (int d = tid; d < DU; d += 256) {
        float sum = 0.f;
#pragma unroll 8
        for (int s = 0; s < TIN; s++) sum += sc[s] * encb[(size_t)s * DU + d];
        g_att[(size_t)bt * DU + d] = sum;
    }
}

// ------------------------- persistent LSTM recurrence ------------------------
// g_hs layout [t][d][b]: h-stores coalesced (128B/warp); next-step staging is
// a straight float4 64KB copy into smem. Barrier: red.release + ld.acquire.
#define LSTM_SMEM ((DU*BB + DU*16 + 4*4*BB) * 4)

__global__ __launch_bounds__(128)
void lstm_kernel(const float* __restrict__ h0,
                 const float* __restrict__ c0,
                 float* __restrict__ out_h,
                 float* __restrict__ out_c) {
    extern __shared__ float smemf[];
    float*  sh  = smemf;                    // [512 d][32 b]
    float4* sW4 = (float4*)(smemf + DU*BB);
    float*  zx  = smemf + DU*BB + DU*16;

    const int tid = threadIdx.x;
    const int b = tid & 31, q = tid >> 5;
    const int d0 = blockIdx.x * 4;
    const unsigned nblk = gridDim.x;

    {
        const float4* src = (const float4*)&g_WhP[(size_t)blockIdx.x * 8192];
        for (int i = tid; i < 2048; i += 128) sW4[i] = src[i];
    }

    float c = c0[(size_t)b*DU + d0 + q];
    float hlast = 0.f;

    for (int t = 0; t < TOUT; t++) {
        if (t == 0) {
            // h0 is [b][d]; transpose into sh[d][b] (one-time)
            for (int i = tid; i < BB*DU; i += 128) {
                int bb = i >> 9, k = i & 511;
                sh[k*32 + bb] = __ldcg(&h0[i]);
            }
        } else {
            // g_hs[t-1] is [d][b] contiguous: straight float4 copy
            const float4* src = (const float4*)(g_hs + (size_t)(t-1)*BB*DU);
            float4* dst = (float4*)sh;
            for (int i = tid; i < (BB*DU)/4; i += 128)
                dst[i] = __ldcg(&src[i]);
        }
        __syncthreads();

        float4 z = *(const float4*)(&g_zin[((size_t)b*TOUT + t)*(4*DU) + q*DU + d0]);
        float a0 = z.x, a1 = z.y, a2 = z.z, a3 = z.w;
#pragma unroll 8
        for (int k = 0; k < DU; k++) {
            float hv = sh[k*32 + b];
            float4 wv = sW4[k*4 + q];
            a0 += hv * wv.x; a1 += hv * wv.y; a2 += hv * wv.z; a3 += hv * wv.w;
        }
        zx[(q*4 + 0)*32 + b] = a0;
        zx[(q*4 + 1)*32 + b] = a1;
        zx[(q*4 + 2)*32 + b] = a2;
        zx[(q*4 + 3)*32 + b] = a3;
        __syncthreads();

        float zi = zx[(0*4 + q)*32 + b];
        float zf = zx[(1*4 + q)*32 + b];
        float zg = zx[(2*4 + q)*32 + b];
        float zo = zx[(3*4 + q)*32 + b];
        float fi = 1.f / (1.f + expf(-zi));
        float ff = 1.f / (1.f + expf(-zf));
        float gg = tanhf(zg);
        float oo = 1.f / (1.f + expf(-zo));
        c = ff * c + fi * gg;
        float h = oo * tanhf(c);
        hlast = h;
        // coalesced store: [t][d][b]
        g_hs[(size_t)t*BB*DU + (d0 + q)*32 + b] = h;
        // fp16 copy in GEMM layout [b*TOUT+t][d]
        g_hs16[((size_t)b*TOUT + t)*DU + d0 + q] = __float2half_rn(h);
        // prefetch next step's zin line into L2
        if (t + 1 < TOUT)
            asm volatile("prefetch.global.L2 [%0];"
                         :: "l"(&g_zin[((size_t)b*TOUT + t + 1)*(4*DU) + q*DU + d0]));
        __syncthreads();

        if (tid == 0) {
            unsigned one = 1u;
            asm volatile("red.release.gpu.global.add.u32 [%0], %1;"
                         :: "l"(&g_bar), "r"(one) : "memory");
            unsigned target = (unsigned)(t + 1) * nblk;
            unsigned v;
            do {
                asm volatile("ld.acquire.gpu.global.u32 %0, [%1];"
                             : "=r"(v) : "l"(&g_bar) : "memory");
            } while (v < target);
        }
        __syncthreads();
    }

    out_c[(size_t)b*DU + d0 + q] = c;
    out_h[(size_t)b*DU + d0 + q] = hlast;
}

// ------------------------- host launcher -------------------------------------
extern "C" void kernel_launch(void* const* d_in, const int* in_sizes, int n_in,
                              void* d_out, int out_size) {
    const int*   inputs = (const int*)  d_in[0];
    const float* enc    = (const float*)d_in[1];
    const float* h0     = (const float*)d_in[2];
    const float* c0     = (const float*)d_in[3];
    const float* emb    = (const float*)d_in[4];
    const float* Wq     = (const float*)d_in[5];
    const float* bq     = (const float*)d_in[6];
    const float* Wx     = (const float*)d_in[7];
    const float* Wh     = (const float*)d_in[8];
    const float* b_lstm = (const float*)d_in[9];
    const float* Wfc    = (const float*)d_in[10];
    const float* bfc    = (const float*)d_in[11];

    float* out        = (float*)d_out;
    float* out_logits = out;
    float* out_h      = out + (size_t)N_LOGITS;
    float* out_c      = out_h + N_H;
    float* out_attn   = out_c + N_H;

    float *px, *pq, *pzin;
    __nv_bfloat16 *plin_h, *plin_l, *pWx_h, *pWx_l;
    __half *phs16, *pWfc16;
    cudaGetSymbolAddress((void**)&px,   g_x);
    cudaGetSymbolAddress((void**)&pq,   g_q);
    cudaGetSymbolAddress((void**)&pzin, g_zin);
    cudaGetSymbolAddress((void**)&plin_h, g_lin_h);
    cudaGetSymbolAddress((void**)&plin_l, g_lin_l);
    cudaGetSymbolAddress((void**)&pWx_h,  g_Wx_h);
    cudaGetSymbolAddress((void**)&pWx_l,  g_Wx_l);
    cudaGetSymbolAddress((void**)&phs16,  g_hs16);
    cudaGetSymbolAddress((void**)&pWfc16, g_Wfc16);

    cudaFuncSetAttribute(lstm_kernel,
                         cudaFuncAttributeMaxDynamicSharedMemorySize, LSTM_SMEM);
    cudaFuncSetAttribute(gemm_mma3_kernel,
                         cudaFuncAttributeMaxDynamicSharedMemorySize, GEMM_SMEM);
    cudaFuncSetAttribute(gemm_f16_kernel,
                         cudaFuncAttributeMaxDynamicSharedMemorySize, GEMM16_SMEM);

    zero_bar_kernel<<<1, 1>>>();

    gather_x_kernel<<<(BT*EMB + 255)/256, 256>>>(inputs, emb);

    // q = x @ Wq + bq  (small, fp32)
    sgemm_kernel<<<dim3(DU/128, BT/128), 256>>>(px, Wq, bq, pq, BT, DU, EMB);

    attn_kernel<<<BT, 256>>>(enc, out_attn);

    // weight preprocessing
    split_kernel<<<(KIN*4*DU + 255)/256, 256>>>(Wx, pWx_h, pWx_l, KIN*4*DU);
    wfc_f16_kernel<<<(int)(((size_t)DU*BV + 255)/256), 256>>>(Wfc);
    pack_wh_kernel<<<(128*512*16 + 255)/256, 256>>>(Wh);

    build_lstmin_split_kernel<<<(BT*KIN + 255)/256, 256>>>();

    // Z_in = lstm_in @ Wx + b_lstm   (bf16x3, proven path)
    gemm_mma3_kernel<<<dim3(BT/128, (4*DU)/128), 256, GEMM_SMEM>>>(
        plin_h, plin_l, pWx_h, pWx_l, b_lstm, pzin, BT, 4*DU, KIN);

    lstm_kernel<<<128, 128, LSTM_SMEM>>>(h0, c0, out_h, out_c);

    // logits = fp16(hs) @ fp16(Wfc) + bfc   (single HMMA pass, R14 config)
    gemm_f16_kernel<<<dim3(BV/128, BT/128), 256, GEMM16_SMEM>>>(
        phs16, pWfc16, bfc, out_logits, BT, BV, DU);
}

// round 17
// speedup vs baseline: 1.4037x; 1.4037x over previous
#include <cuda_runtime.h>
#include <cuda_bf16.h>
#include <cuda_fp16.h>
#include <math.h>
#include <cstdint>

// Problem dims
#define BV 32000
#define EMB 256
#define DU 512
#define BB 32
#define TIN 64
#define TOUT 64
#define BT (BB*TOUT)          // 2048
#define KIN (DU+EMB)          // 768

#define N_LOGITS  (BT*BV)
#define N_H       (BB*DU)

// ------------------------- scratch (static device globals) -------------------
__device__ float g_x[BT*EMB];
__device__ float g_q[BT*DU];
__device__ float g_att[BT*DU];
__device__ float g_zin[BT*4*DU];
__device__ float g_hs[TOUT*BB*DU];      // layout: [t][d][b]
__device__ float g_WhP[128*512*16];
__device__ unsigned g_bar;

// bf16 split operands for Zin GEMM
__device__ __align__(16) __nv_bfloat16 g_lin_h[BT*KIN],  g_lin_l[BT*KIN];
__device__ __align__(16) __nv_bfloat16 g_Wx_h[KIN*4*DU], g_Wx_l[KIN*4*DU];

// fp16 operands for logits GEMM (A = fp16(hs) [b*TOUT+t][d], B = fp16(Wfc))
__device__ __align__(16) __half g_hs16[BT*DU];
__device__ __align__(16) __half g_Wfc16[(size_t)DU*BV];

// ------------------------- tiny kernels --------------------------------------
__global__ void zero_bar_kernel() { g_bar = 0u; }

__global__ void gather_x_kernel(const int* __restrict__ inp,
                                const float* __restrict__ emb) {
    int i = blockIdx.x * blockDim.x + threadIdx.x;
    if (i >= BT*EMB) return;
    int bt = i >> 8, e = i & 255;
    g_x[i] = emb[(size_t)inp[bt] * EMB + e];
}

__device__ __forceinline__ void split_store(float v, __nv_bfloat16* hi,
                                            __nv_bfloat16* lo, size_t i) {
    __nv_bfloat16 h = __float2bfloat16(v);
    hi[i] = h;
    lo[i] = __float2bfloat16(v - __bfloat162float(h));
}

__global__ void split_kernel(const float* __restrict__ in,
                             __nv_bfloat16* __restrict__ hi,
                             __nv_bfloat16* __restrict__ lo, int n) {
    int i = blockIdx.x * blockDim.x + threadIdx.x;
    if (i >= n) return;
    split_store(in[i], hi, lo, i);
}

__global__ void build_lstmin_split_kernel() {
    int i = blockIdx.x * blockDim.x + threadIdx.x;
    if (i >= BT*KIN) return;
    int bt = i / KIN, j = i % KIN;
    float v = (j < DU) ? g_att[bt*DU + j] : g_x[bt*EMB + (j-DU)];
    split_store(v, g_lin_h, g_lin_l, i);
}

__global__ void pack_wh_kernel(const float* __restrict__ Wh) {
    int i = blockIdx.x * blockDim.x + threadIdx.x;
    if (i >= 128*512*16) return;
    int blk = i >> 13;
    int rem = i & 8191;
    int k = rem >> 4, t = rem & 15;
    int q = t >> 2, j = t & 3;
    g_WhP[i] = Wh[(size_t)k*2048 + q*512 + blk*4 + j];
}

// Wfc [512, 32000] fp32 -> fp16 (same layout)
__global__ void wfc_f16_kernel(const float* __restrict__ Wfc) {
    size_t i = (size_t)blockIdx.x * blockDim.x + threadIdx.x;
    if (i >= (size_t)DU*BV) return;
    g_Wfc16[i] = __float2half_rn(Wfc[i]);
}

// g_hs [t][d][b] fp32 -> g_hs16 [b*TOUT+t][d] fp16 (smem-tiled transpose)
__global__ __launch_bounds__(256)
void hs16_kernel() {
    __shared__ float tile[32][33];
    const int t  = blockIdx.y;
    const int d0 = blockIdx.x * 32;
    const int tx = threadIdx.x & 31, ty = threadIdx.x >> 5;   // 32 x 8
#pragma unroll
    for (int i = 0; i < 4; i++) {
        int dd = ty + i*8;
        tile[dd][tx] = g_hs[(size_t)t*BB*DU + (d0 + dd)*32 + tx];
    }
    __syncthreads();
#pragma unroll
    for (int i = 0; i < 4; i++) {
        int b = ty + i*8;
        g_hs16[((size_t)b*TOUT + t)*DU + d0 + tx] = __float2half_rn(tile[tx][b]);
    }
}

// ------------------------- scalar fp32 SGEMM (small q GEMM only) -------------
__global__ __launch_bounds__(256)
void sgemm_kernel(const float* __restrict__ A, const float* __restrict__ B,
                  const float* __restrict__ bias, float* __restrict__ C,
                  int M, int N, int K) {
    __shared__ float As[8][128];
    __shared__ float Bs[8][128];
    const int tid = threadIdx.x;
    const int tx = tid & 15, ty = tid >> 4;
    const int row0 = blockIdx.y * 128, col0 = blockIdx.x * 128;

    float acc[8][8];
#pragma unroll
    for (int i = 0; i < 8; i++)
#pragma unroll
        for (int j = 0; j < 8; j++) acc[i][j] = 0.f;

    for (int k0 = 0; k0 < K; k0 += 8) {
#pragma unroll
        for (int l = 0; l < 4; l++) {
            int idx = tid + l*256;
            int r = idx >> 3, kk = idx & 7;
            As[kk][r] = A[(size_t)(row0 + r) * K + k0 + kk];
        }
#pragma unroll
        for (int l = 0; l < 4; l++) {
            int idx = tid + l*256;
            int kk = idx >> 7, c = idx & 127;
            Bs[kk][c] = B[(size_t)(k0 + kk) * N + col0 + c];
        }
        __syncthreads();
#pragma unroll
        for (int kk = 0; kk < 8; kk++) {
            float a[8], b[8];
#pragma unroll
            for (int i = 0; i < 8; i++) a[i] = As[kk][ty*8 + i];
#pragma unroll
            for (int j = 0; j < 8; j++) b[j] = Bs[kk][tx*8 + j];
#pragma unroll
            for (int i = 0; i < 8; i++)
#pragma unroll
                for (int j = 0; j < 8; j++) acc[i][j] += a[i] * b[j];
        }
        __syncthreads();
    }
#pragma unroll
    for (int i = 0; i < 8; i++) {
        size_t r = row0 + ty*8 + i;
#pragma unroll
        for (int j = 0; j < 8; j++) {
            int cc = col0 + tx*8 + j;
            C[r * N + cc] = acc[i][j] + bias[cc];
        }
    }
}

// ------------------------- common PTX helpers --------------------------------
__device__ __forceinline__ uint32_t smem_u32(const void* p) {
    return (uint32_t)__cvta_generic_to_shared(p);
}
__device__ __forceinline__ void cp16(void* dst, const void* src) {
    uint32_t d = smem_u32(dst);
    asm volatile("cp.async.cg.shared.global [%0], [%1], 16;"
                 :: "r"(d), "l"(src) : "memory");
}
__device__ __forceinline__ void cp_commit() {
    asm volatile("cp.async.commit_group;" ::: "memory");
}
__device__ __forceinline__ void cp_wait1() {
    asm volatile("cp.async.wait_group 1;" ::: "memory");
}
__device__ __forceinline__ void ldsm_x4(unsigned* r, uint32_t addr) {
    asm volatile("ldmatrix.sync.aligned.m8n8.x4.shared.b16 {%0,%1,%2,%3}, [%4];"
                 : "=r"(r[0]), "=r"(r[1]), "=r"(r[2]), "=r"(r[3]) : "r"(addr));
}
__device__ __forceinline__ void ldsm_x4_t(unsigned* r, uint32_t addr) {
    asm volatile("ldmatrix.sync.aligned.m8n8.x4.trans.shared.b16 {%0,%1,%2,%3}, [%4];"
                 : "=r"(r[0]), "=r"(r[1]), "=r"(r[2]), "=r"(r[3]) : "r"(addr));
}
__device__ __forceinline__ void mma16816(float* c, const unsigned* a,
                                         unsigned b0, unsigned b1) {
    asm volatile(
        "mma.sync.aligned.m16n8k16.row.col.f32.bf16.bf16.f32 "
        "{%0,%1,%2,%3}, {%4,%5,%6,%7}, {%8,%9}, {%0,%1,%2,%3};"
        : "+f"(c[0]), "+f"(c[1]), "+f"(c[2]), "+f"(c[3])
        : "r"(a[0]), "r"(a[1]), "r"(a[2]), "r"(a[3]), "r"(b0), "r"(b1));
}
__device__ __forceinline__ void mma16816h(float* c, const unsigned* a,
                                          unsigned b0, unsigned b1) {
    asm volatile(
        "mma.sync.aligned.m16n8k16.row.col.f32.f16.f16.f32 "
        "{%0,%1,%2,%3}, {%4,%5,%6,%7}, {%8,%9}, {%0,%1,%2,%3};"
        : "+f"(c[0]), "+f"(c[1]), "+f"(c[2]), "+f"(c[3])
        : "r"(a[0]), "r"(a[1]), "r"(a[2]), "r"(a[3]), "r"(b0), "r"(b1));
}

// ------------------------- bf16x3 mma GEMM (Zin only) ------------------------
#define BKC 32
#define OFF_AL_B 10240
#define OFF_BH_B 20480
#define OFF_BL_B 29184
#define STAGE_B  37888
#define GEMM_SMEM (2*STAGE_B)

__device__ __forceinline__ void gemm_issue(
        const __nv_bfloat16* Ah, const __nv_bfloat16* Al,
        const __nv_bfloat16* Bh, const __nv_bfloat16* Bl,
        char* smc, int ch, int tid, int row0, int col0, int K, int N) {
    char* sb = smc + (ch & 1) * STAGE_B;
    const int k0 = ch * BKC;
#pragma unroll
    for (int l = 0; l < 2; l++) {
        int c = tid*2 + l;
        int r = c >> 2, q = c & 3;
        size_t g = (size_t)(row0 + r) * K + k0 + q*8;
        cp16(sb + r*80 + q*16, Ah + g);
        cp16(sb + OFF_AL_B + r*80 + q*16, Al + g);
    }
#pragma unroll
    for (int l = 0; l < 2; l++) {
        int c = tid*2 + l;
        int r = c >> 4, q = c & 15;
        size_t g = (size_t)(k0 + r) * N + col0 + q*8;
        cp16(sb + OFF_BH_B + r*272 + q*16, Bh + g);
        cp16(sb + OFF_BL_B + r*272 + q*16, Bl + g);
    }
    cp_commit();
}

__global__ __launch_bounds__(256, 2)
void gemm_mma3_kernel(const __nv_bfloat16* __restrict__ Ah,
                      const __nv_bfloat16* __restrict__ Al,
                      const __nv_bfloat16* __restrict__ Bh,
                      const __nv_bfloat16* __restrict__ Bl,
                      const float* __restrict__ bias,
                      float* __restrict__ C,
                      int M, int N, int K) {
    extern __shared__ char smc[];
    const uint32_t sbase = smem_u32(smc);
    const int tid  = threadIdx.x;
    const int lane = tid & 31;
    const int warp = tid >> 5;
    const int wm = warp & 1;
    const int wn = warp >> 1;
    const int row0 = blockIdx.x * 128;
    const int col0 = blockIdx.y * 128;

    float acc[4][4][4];
#pragma unroll
    for (int i = 0; i < 4; i++)
#pragma unroll
        for (int j = 0; j < 4; j++)
#pragma unroll
            for (int r = 0; r < 4; r++) acc[i][j][r] = 0.f;

    const int grp = lane >> 3;
    const unsigned a_row  = (lane & 15);
    const unsigned a_koff = (lane >> 4) << 3;
    const unsigned b_row  = ((grp & 1) << 3) + (lane & 7);
    const unsigned b_coff = wn*32 + ((grp >> 1) << 3);

    const int nch = K / BKC;
    gemm_issue(Ah, Al, Bh, Bl, smc, 0, tid, row0, col0, K, N);
    if (nch > 1) gemm_issue(Ah, Al, Bh, Bl, smc, 1, tid, row0, col0, K, N);
    else cp_commit();

    for (int ch = 0; ch < nch; ch++) {
        cp_wait1();
        __syncthreads();

        const uint32_t st = sbase + (ch & 1) * STAGE_B;
        const uint32_t aH = st, aL = st + OFF_AL_B;
        const uint32_t bH = st + OFF_BH_B, bL = st + OFF_BL_B;
#pragma unroll
        for (int kk = 0; kk < BKC; kk += 16) {
            unsigned b_h[2][4], b_l[2][4];
#pragma unroll
            for (int p = 0; p < 2; p++) {
                uint32_t off = ((kk + b_row) * 136 + b_coff + p*16) * 2;
                ldsm_x4_t(b_h[p], bH + off);
                ldsm_x4_t(b_l[p], bL + off);
            }
#pragma unroll
            for (int mt = 0; mt < 4; mt++) {
                unsigned a_h[4], a_l[4];
                uint32_t off = ((wm*64 + mt*16 + a_row) * 40 + kk + a_koff) * 2;
                ldsm_x4(a_h, aH + off);
                ldsm_x4(a_l, aL + off);
#pragma unroll
                for (int p = 0; p < 2; p++)
#pragma unroll
                    for (int hf = 0; hf < 2; hf++) {
                        int nt = p*2 + hf;
                        unsigned bh0 = b_h[p][hf*2], bh1 = b_h[p][hf*2+1];
                        unsigned bl0 = b_l[p][hf*2], bl1 = b_l[p][hf*2+1];
                        mma16816(acc[mt][nt], a_h, bh0, bh1);
                        mma16816(acc[mt][nt], a_h, bl0, bl1);
                        mma16816(acc[mt][nt], a_l, bh0, bh1);
                    }
            }
        }
        __syncthreads();
        if (ch + 2 < nch)
            gemm_issue(Ah, Al, Bh, Bl, smc, ch + 2, tid, row0, col0, K, N);
        else
            cp_commit();
    }

#pragma unroll
    for (int mt = 0; mt < 4; mt++) {
        int r_up = row0 + wm*64 + mt*16 + (lane >> 2);
        int r_dn = r_up + 8;
#pragma unroll
        for (int nt = 0; nt < 4; nt++) {
            int cc = col0 + wn*32 + nt*8 + (lane & 3)*2;
            float b0 = bias[cc], b1 = bias[cc+1];
            *(float2*)&C[(size_t)r_up * N + cc] =
                make_float2(acc[mt][nt][0] + b0, acc[mt][nt][1] + b1);
            *(float2*)&C[(size_t)r_dn * N + cc] =
                make_float2(acc[mt][nt][2] + b0, acc[mt][nt][3] + b1);
        }
    }
}

// ------------------------- fp16 single-pass mma GEMM (logits, R14 config) ----
#define F16_B   10240
#define F16_STG 18944
#define GEMM16_SMEM (3*F16_STG)

__device__ __forceinline__ void f16_issue(
        const __half* A, const __half* B,
        char* smc, int ch, int tid, int row0, int col0, int K, int N) {
    char* sb = smc + (ch % 3) * F16_STG;
    const int k0 = ch * BKC;
#pragma unroll
    for (int l = 0; l < 2; l++) {
        int c = tid*2 + l;                 // 0..511
        int r = c >> 2, q = c & 3;         // A: 128 rows x 4 x 16B
        size_t g = (size_t)(row0 + r) * K + k0 + q*8;
        cp16(sb + r*80 + q*16, A + g);
    }
#pragma unroll
    for (int l = 0; l < 2; l++) {
        int c = tid*2 + l;
        int r = c >> 4, q = c & 15;        // B: 32 rows x 16 x 16B
        size_t g = (size_t)(k0 + r) * N + col0 + q*8;
        cp16(sb + F16_B + r*272 + q*16, B + g);
    }
    cp_commit();
}

__global__ __launch_bounds__(256, 2)
void gemm_f16_kernel(const __half* __restrict__ A,
                     const __half* __restrict__ B,
                     const float* __restrict__ bias,
                     float* __restrict__ C,
                     int M, int N, int K) {
    extern __shared__ char smc[];
    const uint32_t sbase = smem_u32(smc);
    const int tid  = threadIdx.x;
    const int lane = tid & 31;
    const int warp = tid >> 5;
    const int wm = warp & 1;
    const int wn = warp >> 1;
    const int row0 = blockIdx.y * 128;
    const int col0 = blockIdx.x * 128;

    float acc[4][4][4];
#pragma unroll
    for (int i = 0; i < 4; i++)
#pragma unroll
        for (int j = 0; j < 4; j++)
#pragma unroll
            for (int r = 0; r < 4; r++) acc[i][j][r] = 0.f;

    const int grp = lane >> 3;
    const unsigned a_row  = (lane & 15);
    const unsigned a_koff = (lane >> 4) << 3;
    const unsigned b_row  = ((grp & 1) << 3) + (lane & 7);
    const unsigned b_coff = wn*32 + ((grp >> 1) << 3);

    const int nch = K / BKC;               // 16 for K=512
    f16_issue(A, B, smc, 0, tid, row0, col0, K, N);
    if (nch > 1) f16_issue(A, B, smc, 1, tid, row0, col0, K, N);
    else cp_commit();

    for (int ch = 0; ch < nch; ch++) {
        cp_wait1();
        __syncthreads();
        if (ch + 2 < nch)
            f16_issue(A, B, smc, ch + 2, tid, row0, col0, K, N);
        else
            cp_commit();

        const uint32_t st = sbase + (ch % 3) * F16_STG;
        const uint32_t aP = st;
        const uint32_t bP = st + F16_B;
#pragma unroll
        for (int kk = 0; kk < BKC; kk += 16) {
            unsigned b_f[2][4];
#pragma unroll
            for (int p = 0; p < 2; p++) {
                uint32_t off = ((kk + b_row) * 136 + b_coff + p*16) * 2;
                ldsm_x4_t(b_f[p], bP + off);
            }
#pragma unroll
            for (int mt = 0; mt < 4; mt++) {
                unsigned a_f[4];
                uint32_t off = ((wm*64 + mt*16 + a_row) * 40 + kk + a_koff) * 2;
                ldsm_x4(a_f, aP + off);
#pragma unroll
                for (int p = 0; p < 2; p++)
#pragma unroll
                    for (int hf = 0; hf < 2; hf++) {
                        int nt = p*2 + hf;
                        mma16816h(acc[mt][nt], a_f, b_f[p][hf*2], b_f[p][hf*2+1]);
                    }
            }
        }
        __syncthreads();
    }

#pragma unroll
    for (int mt = 0; mt < 4; mt++) {
        int r_up = row0 + wm*64 + mt*16 + (lane >> 2);
        int r_dn = r_up + 8;
#pragma unroll
        for (int nt = 0; nt < 4; nt++) {
            int cc = col0 + wn*32 + nt*8 + (lane & 3)*2;
            float b0 = bias[cc], b1 = bias[cc+1];
            *(float2*)&C[(size_t)r_up * N + cc] =
                make_float2(acc[mt][nt][0] + b0, acc[mt][nt][1] + b1);
            *(float2*)&C[(size_t)r_dn * N + cc] =
                make_float2(acc[mt][nt][2] + b0, acc[mt][nt][3] + b1);
        }
    }
}

// ------------------------- attention (one block per (b,t)) -------------------
__global__ __launch_bounds__(256)
void attn_kernel(const float* __restrict__ enc, float* __restrict__ attn_out) {
    int bt = blockIdx.x;
    int b = bt >> 6;
    __shared__ float sq[DU];
    __shared__ float sc[TIN];
    __shared__ float red[2];
    int tid = threadIdx.x;
    int w = tid >> 5, lane = tid & 31;

    for (int i = tid; i < DU; i += 256) sq[i] = g_q[(size_t)bt*DU + i];
    __syncthreads();

    const float* encb = enc + (size_t)b * TIN * DU;
    for (int s = w; s < TIN; s += 8) {
        const float* e = encb + (size_t)s * DU;
        float sum = 0.f;
        for (int d = lane; d < DU; d += 32) sum += sq[d] * e[d];
#pragma unroll
        for (int o = 16; o > 0; o >>= 1) sum += __shfl_xor_sync(0xffffffffu, sum, o);
        if (lane == 0) sc[s] = sum;
    }
    __syncthreads();

    if (w == 0) {
        float v = fmaxf(sc[lane], sc[lane + 32]);
#pragma unroll
        for (int o = 16; o > 0; o >>= 1) v = fmaxf(v, __shfl_xor_sync(0xffffffffu, v, o));
        if (lane == 0) red[0] = v;
    }
    __syncthreads();
    float m = red[0];
    if (tid < TIN) sc[tid] = expf(sc[tid] - m);
    __syncthreads();
    if (w == 0) {
        float v = sc[lane] + sc[lane + 32];
#pragma unroll
        for (int o = 16; o > 0; o >>= 1) v += __shfl_xor_sync(0xffffffffu, v, o);
        if (lane == 0) red[1] = v;
    }
    __syncthreads();
    float inv = 1.f / red[1];
    if (tid < TIN) {
        float wv = sc[tid] * inv;
        sc[tid] = wv;
        attn_out[(size_t)bt * TIN + tid] = wv;
    }
    __syncthreads();

    for (int d = tid; d < DU; d += 256) {
        float sum = 0.f;
#pragma unroll 8
        for (int s = 0; s < TIN; s++) sum += sc[s] * encb[(size_t)s * DU + d];
        g_att[(size_t)bt * DU + d] = sum;
    }
}

// ------------------------- persistent LSTM recurrence ------------------------
// g_hs layout [t][d][b]: coalesced stores + straight float4 staging copy.
// Barrier: red.release + ld.acquire. fp16 conversion moved OUT of the loop.
#define LSTM_SMEM ((DU*BB + DU*16 + 4*4*BB) * 4)

__global__ __launch_bounds__(128)
void lstm_kernel(const float* __restrict__ h0,
                 const float* __restrict__ c0,
                 float* __restrict__ out_h,
                 float* __restrict__ out_c) {
    extern __shared__ float smemf[];
    float*  sh  = smemf;                    // [512 d][32 b]
    float4* sW4 = (float4*)(smemf + DU*BB);
    float*  zx  = smemf + DU*BB + DU*16;

    const int tid = threadIdx.x;
    const int b = tid & 31, q = tid >> 5;
    const int d0 = blockIdx.x * 4;
    const unsigned nblk = gridDim.x;

    {
        const float4* src = (const float4*)&g_WhP[(size_t)blockIdx.x * 8192];
        for (int i = tid; i < 2048; i += 128) sW4[i] = src[i];
    }

    float c = c0[(size_t)b*DU + d0 + q];
    float hlast = 0.f;

    for (int t = 0; t < TOUT; t++) {
        if (t == 0) {
            for (int i = tid; i < BB*DU; i += 128) {
                int bb = i >> 9, k = i & 511;
                sh[k*32 + bb] = __ldcg(&h0[i]);
            }
        } else {
            const float4* src = (const float4*)(g_hs + (size_t)(t-1)*BB*DU);
            float4* dst = (float4*)sh;
            for (int i = tid; i < (BB*DU)/4; i += 128)
                dst[i] = __ldcg(&src[i]);
        }
        __syncthreads();

        float4 z = *(const float4*)(&g_zin[((size_t)b*TOUT + t)*(4*DU) + q*DU + d0]);
        float a0 = z.x, a1 = z.y, a2 = z.z, a3 = z.w;
#pragma unroll 8
        for (int k = 0; k < DU; k++) {
            float hv = sh[k*32 + b];
            float4 wv = sW4[k*4 + q];
            a0 += hv * wv.x; a1 += hv * wv.y; a2 += hv * wv.z; a3 += hv * wv.w;
        }
        zx[(q*4 + 0)*32 + b] = a0;
        zx[(q*4 + 1)*32 + b] = a1;
        zx[(q*4 + 2)*32 + b] = a2;
        zx[(q*4 + 3)*32 + b] = a3;
        __syncthreads();

        float zi = zx[(0*4 + q)*32 + b];
        float zf = zx[(1*4 + q)*32 + b];
        float zg = zx[(2*4 + q)*32 + b];
        float zo = zx[(3*4 + q)*32 + b];
        float fi = 1.f / (1.f + expf(-zi));
        float ff = 1.f / (1.f + expf(-zf));
        float gg = tanhf(zg);
        float oo = 1.f / (1.f + expf(-zo));
        c = ff * c + fi * gg;
        float h = oo * tanhf(c);
        hlast = h;
        g_hs[(size_t)t*BB*DU + (d0 + q)*32 + b] = h;   // coalesced [t][d][b]
        __syncthreads();

        if (tid == 0) {
            unsigned one = 1u;
            asm volatile("red.release.gpu.global.add.u32 [%0], %1;"
                         :: "l"(&g_bar), "r"(one) : "memory");
            unsigned target = (unsigned)(t + 1) * nblk;
            unsigned v;
            do {
                asm volatile("ld.acquire.gpu.global.u32 %0, [%1];"
                             : "=r"(v) : "l"(&g_bar) : "memory");
            } while (v < target);
        }
        __syncthreads();
    }

    out_c[(size_t)b*DU + d0 + q] = c;
    out_h[(size_t)b*DU + d0 + q] = hlast;
}

// ------------------------- host launcher -------------------------------------
extern "C" void kernel_launch(void* const* d_in, const int* in_sizes, int n_in,
                              void* d_out, int out_size) {
    const int*   inputs = (const int*)  d_in[0];
    const float* enc    = (const float*)d_in[1];
    const float* h0     = (const float*)d_in[2];
    const float* c0     = (const float*)d_in[3];
    const float* emb    = (const float*)d_in[4];
    const float* Wq     = (const float*)d_in[5];
    const float* bq     = (const float*)d_in[6];
    const float* Wx     = (const float*)d_in[7];
    const float* Wh     = (const float*)d_in[8];
    const float* b_lstm = (const float*)d_in[9];
    const float* Wfc    = (const float*)d_in[10];
    const float* bfc    = (const float*)d_in[11];

    float* out        = (float*)d_out;
    float* out_logits = out;
    float* out_h      = out + (size_t)N_LOGITS;
    float* out_c      = out_h + N_H;
    float* out_attn   = out_c + N_H;

    float *px, *pq, *pzin;
    __nv_bfloat16 *plin_h, *plin_l, *pWx_h, *pWx_l;
    __half *phs16, *pWfc16;
    cudaGetSymbolAddress((void**)&px,   g_x);
    cudaGetSymbolAddress((void**)&pq,   g_q);
    cudaGetSymbolAddress((void**)&pzin, g_zin);
    cudaGetSymbolAddress((void**)&plin_h, g_lin_h);
    cudaGetSymbolAddress((void**)&plin_l, g_lin_l);
    cudaGetSymbolAddress((void**)&pWx_h,  g_Wx_h);
    cudaGetSymbolAddress((void**)&pWx_l,  g_Wx_l);
    cudaGetSymbolAddress((void**)&phs16,  g_hs16);
    cudaGetSymbolAddress((void**)&pWfc16, g_Wfc16);

    cudaFuncSetAttribute(lstm_kernel,
                         cudaFuncAttributeMaxDynamicSharedMemorySize, LSTM_SMEM);
    cudaFuncSetAttribute(gemm_mma3_kernel,
                         cudaFuncAttributeMaxDynamicSharedMemorySize, GEMM_SMEM);
    cudaFuncSetAttribute(gemm_f16_kernel,
                         cudaFuncAttributeMaxDynamicSharedMemorySize, GEMM16_SMEM);

    zero_bar_kernel<<<1, 1>>>();

    gather_x_kernel<<<(BT*EMB + 255)/256, 256>>>(inputs, emb);

    // q = x @ Wq + bq  (small, fp32)
    sgemm_kernel<<<dim3(DU/128, BT/128), 256>>>(px, Wq, bq, pq, BT, DU, EMB);

    attn_kernel<<<BT, 256>>>(enc, out_attn);

    // weight preprocessing
    split_kernel<<<(KIN*4*DU + 255)/256, 256>>>(Wx, pWx_h, pWx_l, KIN*4*DU);
    wfc_f16_kernel<<<(int)(((size_t)DU*BV + 255)/256), 256>>>(Wfc);
    pack_wh_kernel<<<(128*512*16 + 255)/256, 256>>>(Wh);

    build_lstmin_split_kernel<<<(BT*KIN + 255)/256, 256>>>();

    // Z_in = lstm_in @ Wx + b_lstm   (bf16x3, proven path)
    gemm_mma3_kernel<<<dim3(BT/128, (4*DU)/128), 256, GEMM_SMEM>>>(
        plin_h, plin_l, pWx_h, pWx_l, b_lstm, pzin, BT, 4*DU, KIN);

    lstm_kernel<<<128, 128, LSTM_SMEM>>>(h0, c0, out_h, out_c);

    // hs fp32 [t][d][b] -> fp16 [b*TOUT+t][d]
    hs16_kernel<<<dim3(DU/32, TOUT), 256>>>();

    // logits = fp16(hs) @ fp16(Wfc) + bfc   (single HMMA pass)
    gemm_f16_kernel<<<dim3(BV/128, BT/128), 256, GEMM16_SMEM>>>(
        phs16, pWfc16, bfc, out_logits, BT, BV, DU);
}